// round 1
// baseline (speedup 1.0000x reference)
#include <cuda_runtime.h>

// Problem constants (from reference setup_inputs)
#define NB 8192
#define NK 512
#define NC 16

#define THREADS 256
#define GROUPS_PER_BLOCK (THREADS / NC)      // 16 examples per block
#define GRID (NB / GROUPS_PER_BLOCK)         // 512 blocks

__device__ float g_partials[GRID];

// One 16-thread group per example b; lane c handles candidate c.
__global__ void __launch_bounds__(THREADS) roc_main_kernel(
    const float* __restrict__ logits,   // [B, K, C]
    const int*   __restrict__ target,   // [B]
    const int*   __restrict__ mask)     // [B, C, K] leading-ones rows
{
    const int tid = blockIdx.x * THREADS + threadIdx.x;
    const int b = tid >> 4;
    const int c = tid & 15;

    // ---- binary search for last k with mask==1 (mask[...,0]==1 guaranteed) ----
    const int* m = mask + ((size_t)b * NC + c) * NK;
    int lo = 0, hi = NK - 1;
    #pragma unroll
    for (int it = 0; it < 9; ++it) {     // 2^9 = 512 -> lo==hi after 9 steps
        int mid = (lo + hi + 1) >> 1;
        if (__ldg(m + mid)) lo = mid; else hi = mid - 1;
    }
    const int counter = lo;              // lengths-1

    // ---- gather logit at last valid timestep ----
    const float x = __ldg(logits + ((size_t)b * NK + counter) * NC + c);

    // ---- log-softmax over the 16 candidates (width-16 shuffles) ----
    const unsigned fm = 0xffffffffu;
    float mx = x;
    #pragma unroll
    for (int o = 8; o; o >>= 1) mx = fmaxf(mx, __shfl_xor_sync(fm, mx, o, 16));
    float s = __expf(x - mx);
    #pragma unroll
    for (int o = 8; o; o >>= 1) s += __shfl_xor_sync(fm, s, o, 16);

    const int tgt = __ldg(target + b);
    const float xt = __shfl_sync(fm, x, tgt, 16);   // lane tgt within 16-lane segment
    const float loss = __logf(s) + mx - xt;          // = logsumexp - x[target]

    // ---- deterministic block reduction (one loss per 16-lane group) ----
    float v = (c == 0) ? loss : 0.0f;
    #pragma unroll
    for (int o = 16; o; o >>= 1) v += __shfl_xor_sync(fm, v, o);  // warp sum

    __shared__ float ssum[THREADS / 32];
    const int warp = threadIdx.x >> 5;
    if ((threadIdx.x & 31) == 0) ssum[warp] = v;
    __syncthreads();
    if (threadIdx.x < (THREADS / 32)) {
        float w = ssum[threadIdx.x];
        #pragma unroll
        for (int o = (THREADS / 64); o; o >>= 1)
            w += __shfl_xor_sync(fm, w, o, THREADS / 32);
        if (threadIdx.x == 0) g_partials[blockIdx.x] = w;
    }
}

// Single-block deterministic final reduction of GRID partials -> mean.
__global__ void __launch_bounds__(GRID) roc_reduce_kernel(float* __restrict__ out)
{
    float v = g_partials[threadIdx.x];
    const unsigned fm = 0xffffffffu;
    #pragma unroll
    for (int o = 16; o; o >>= 1) v += __shfl_xor_sync(fm, v, o);

    __shared__ float ssum[GRID / 32];
    const int warp = threadIdx.x >> 5;
    if ((threadIdx.x & 31) == 0) ssum[warp] = v;
    __syncthreads();
    if (threadIdx.x < (GRID / 32)) {
        float w = ssum[threadIdx.x];
        #pragma unroll
        for (int o = (GRID / 64); o; o >>= 1)
            w += __shfl_xor_sync(fm, w, o, GRID / 32);
        if (threadIdx.x == 0) out[0] = w * (1.0f / (float)NB);
    }
}

extern "C" void kernel_launch(void* const* d_in, const int* in_sizes, int n_in,
                              void* d_out, int out_size)
{
    const float* logits = (const float*)d_in[0];
    const int*   target = (const int*)  d_in[1];
    const int*   mask   = (const int*)  d_in[2];
    float* out = (float*)d_out;

    roc_main_kernel<<<GRID, THREADS>>>(logits, target, mask);
    roc_reduce_kernel<<<1, GRID>>>(out);
}